// round 17
// baseline (speedup 1.0000x reference)
#include <cuda_runtime.h>
#include <math.h>
#include <stdint.h>

#define BSZ   2
#define SEQ   2048
#define DIM   1024
#define NH    16
#define HD    64
#define MTOK  (BSZ * SEQ)       // 4096
#define QKVN  (3 * DIM)         // 3072

// Scratch (no cudaMalloc allowed)
__device__ float g_qkv[(size_t)MTOK * QKVN];   // rna-tf32 values (V third unused)
__device__ float g_vT [(size_t)BSZ * NH * HD * SEQ];  // V transposed [bh][hd][token]
__device__ float g_att[(size_t)MTOK * DIM];    // rna-tf32 values
__device__ float g_xr [(size_t)MTOK * DIM];
__device__ float g_wqr[(size_t)QKVN * DIM];
__device__ float g_wor[(size_t)DIM  * DIM];

// ---------------------------------------------------------------- helpers
__device__ __forceinline__ unsigned f2tf(float x) {
    unsigned r;
    asm("cvt.rna.tf32.f32 %0, %1;" : "=r"(r) : "f"(x));
    return r;
}

__device__ __forceinline__ void mma_tf32(float* c, const unsigned* a,
                                         unsigned b0, unsigned b1) {
    asm volatile(
        "mma.sync.aligned.m16n8k8.row.col.f32.tf32.tf32.f32 "
        "{%0,%1,%2,%3},{%4,%5,%6,%7},{%8,%9},{%0,%1,%2,%3};"
        : "+f"(c[0]), "+f"(c[1]), "+f"(c[2]), "+f"(c[3])
        : "r"(a[0]), "r"(a[1]), "r"(a[2]), "r"(a[3]), "r"(b0), "r"(b1));
}

// ldmatrix x4: four 8x8 b16 tiles. For tf32, each lane's b16-pair == one tf32.
__device__ __forceinline__ void ldsm4(unsigned& r0, unsigned& r1,
                                      unsigned& r2, unsigned& r3, uint32_t addr) {
    asm volatile("ldmatrix.sync.aligned.m8n8.x4.shared.b16 {%0,%1,%2,%3}, [%4];"
        : "=r"(r0), "=r"(r1), "=r"(r2), "=r"(r3) : "r"(addr));
}

__device__ __forceinline__ void cp16(void* smem_dst, const void* gmem_src) {
    unsigned s = (unsigned)__cvta_generic_to_shared(smem_dst);
    asm volatile("cp.async.cg.shared.global [%0], [%1], 16;\n" :: "r"(s), "l"(gmem_src));
}
__device__ __forceinline__ void cp_commit() {
    asm volatile("cp.async.commit_group;\n");
}
template <int N>
__device__ __forceinline__ void cp_wait() {
    asm volatile("cp.async.wait_group %0;\n" :: "n"(N));
}
__device__ __forceinline__ uint32_t smem_u32(const void* p) {
    return (uint32_t)__cvta_generic_to_shared(p);
}

// ----------------------------------------------------------------------------
// Pre-pass: round fp32 -> rna-tf32
// ----------------------------------------------------------------------------
__global__ void round_tf32_kernel(const float* __restrict__ in,
                                  float* __restrict__ out, int n4) {
    int i = blockIdx.x * blockDim.x + threadIdx.x;
    if (i < n4) {
        float4 v = ((const float4*)in)[i];
        float4 o;
        o.x = __uint_as_float(f2tf(v.x));
        o.y = __uint_as_float(f2tf(v.y));
        o.z = __uint_as_float(f2tf(v.z));
        o.w = __uint_as_float(f2tf(v.w));
        ((float4*)out)[i] = o;
    }
}

// ----------------------------------------------------------------------------
// C[M,N] = A[M,K] @ B[N,K]^T via tf32 mma, 3-stage cp.async ring, 1 barrier/chunk.
// ldmatrix fragment loads; xor-swizzled 32-float smem rows; pre-rounded inputs.
// If vT != nullptr and the tile lies in the V region (col >= 2*DIM), the
// epilogue writes TRANSPOSED into vT[bh][hd][token] (rounded) instead of C.
// ----------------------------------------------------------------------------
#define G_STAGE  (128 * 32)
#define GEMM_SMEM (6 * G_STAGE * 4)         // 96 KB

template <bool ROUND>
__global__ void __launch_bounds__(256, 2)
gemm_tf32_kernel(const float* __restrict__ A, const float* __restrict__ B,
                 float* __restrict__ C, float* __restrict__ vT,
                 int M, int N, int K) {
    extern __shared__ float gsm[];
    float* Asm = gsm;                 // [3][128][32] swizzled
    float* Bsm = gsm + 3 * G_STAGE;

    const int tid  = threadIdx.x;
    const int lane = tid & 31;
    const int warp = tid >> 5;
    const int g    = lane >> 2;
    const int tg   = lane & 3;
    const int wm   = (warp >> 2) * 64;
    const int wn   = (warp & 3) * 32;
    const int m0   = blockIdx.y * 128;
    const int n0   = blockIdx.x * 128;

    const int ldr = tid >> 3;
    const int ldb = tid & 7;

    // ldmatrix per-lane constants
    const int l7  = lane & 7;
    const int rA8 = ((lane >> 3) & 1) * 8;
    const int gA  = lane >> 4;
    const int rB8 = (lane >> 4) * 8;
    const int gB  = (lane >> 3) & 1;

    uint32_t arow[4], brow[2];
#pragma unroll
    for (int mt = 0; mt < 4; mt++) arow[mt] = (wm + mt * 16 + rA8 + l7) * 128u;
#pragma unroll
    for (int np = 0; np < 2; np++) brow[np] = (wn + np * 16 + rB8 + l7) * 128u;

    uint32_t AbS[3], BbS[3];
#pragma unroll
    for (int s = 0; s < 3; s++) {
        AbS[s] = smem_u32(Asm + s * G_STAGE);
        BbS[s] = smem_u32(Bsm + s * G_STAGE);
    }

    float c[4][4][4];
#pragma unroll
    for (int mt = 0; mt < 4; mt++)
#pragma unroll
        for (int nt = 0; nt < 4; nt++)
#pragma unroll
            for (int i = 0; i < 4; i++) c[mt][nt][i] = 0.0f;

    const int nIter = K >> 5;

    auto load_chunk = [&](int s, int ch) {
        float* As = Asm + s * G_STAGE;
        float* Bs = Bsm + s * G_STAGE;
        const int k0 = ch << 5;
#pragma unroll
        for (int i = 0; i < 4; i++) {
            int r  = ldr + i * 32;
            int sc = ((ldb ^ (r & 7)) << 2);
            cp16(&As[r * 32 + sc], &A[(size_t)(m0 + r) * K + k0 + ldb * 4]);
            cp16(&Bs[r * 32 + sc], &B[(size_t)(n0 + r) * K + k0 + ldb * 4]);
        }
        cp_commit();
    };

    load_chunk(0, 0);
    load_chunk(1, 1);

#pragma unroll 1
    for (int it = 0; it < nIter; it++) {
        if (it + 1 < nIter) cp_wait<1>(); else cp_wait<0>();
        __syncthreads();
        if (it + 2 < nIter) load_chunk((it + 2) % 3, it + 2);

        const int st = it % 3;
        const uint32_t Ab = AbS[st];
        const uint32_t Bb = BbS[st];
#pragma unroll
        for (int k8 = 0; k8 < 4; k8++) {
            const uint32_t swA = (uint32_t)(((2 * k8 + gA) ^ l7) << 4);
            const uint32_t swB = (uint32_t)(((2 * k8 + gB) ^ l7) << 4);
            unsigned a[4][4], b[4][2];
#pragma unroll
            for (int mt = 0; mt < 4; mt++)
                ldsm4(a[mt][0], a[mt][1], a[mt][2], a[mt][3], Ab + arow[mt] + swA);
            ldsm4(b[0][0], b[0][1], b[1][0], b[1][1], Bb + brow[0] + swB);
            ldsm4(b[2][0], b[2][1], b[3][0], b[3][1], Bb + brow[1] + swB);
#pragma unroll
            for (int mt = 0; mt < 4; mt++)
#pragma unroll
                for (int nt = 0; nt < 4; nt++)
                    mma_tf32(c[mt][nt], a[mt], b[nt][0], b[nt][1]);
        }
    }

    const bool vtile = (vT != nullptr) && (n0 >= 2 * DIM);
#pragma unroll
    for (int mt = 0; mt < 4; mt++)
#pragma unroll
        for (int nt = 0; nt < 4; nt++) {
            int row = m0 + wm + mt * 16 + g;
            int col = n0 + wn + nt * 8 + tg * 2;
            float v0 = c[mt][nt][0], v1 = c[mt][nt][1];
            float v2 = c[mt][nt][2], v3 = c[mt][nt][3];
            if (ROUND) {
                v0 = __uint_as_float(f2tf(v0));
                v1 = __uint_as_float(f2tf(v1));
                v2 = __uint_as_float(f2tf(v2));
                v3 = __uint_as_float(f2tf(v3));
            }
            if (vtile) {
                // V region: write transposed vT[bh][hd][token]
                int bb  = row >> 11;           // token row -> batch
                int t   = row & 2047;
                int vc  = col - 2 * DIM;
                int hh  = vc >> 6;
                int hd  = vc & 63;
                float* dst = vT + ((size_t)(bb * NH + hh) * HD + hd) * SEQ + t;
                dst[0]        = v0;            // (hd,   t)
                dst[SEQ]      = v1;            // (hd+1, t)
                dst[8]        = v2;            // (hd,   t+8)
                dst[SEQ + 8]  = v3;            // (hd+1, t+8)
            } else {
                *(float2*)&C[(size_t)row * N + col]       = make_float2(v0, v1);
                *(float2*)&C[(size_t)(row + 8) * N + col] = make_float2(v2, v3);
            }
        }
}

// ----------------------------------------------------------------------------
// Flash attention (causal), tf32 mma, 2-stage cp.async, occ=2.
// ONE barrier per kt; warp-level skip of fully-masked tiles (min-row guard).
// K, P, Q AND V fragments all via ldmatrix.x4 (V is pre-transposed in g_vT).
// ----------------------------------------------------------------------------
#define QP_PAD 68
#define K_PAD  68
#define VT_PAD 68
#define K_STAGE  (64 * K_PAD)
#define VT_STAGE (64 * VT_PAD)
#define ATTN_SMEM ((128 * QP_PAD + 2 * K_STAGE + 2 * VT_STAGE) * 4)

__device__ __forceinline__ void attn_prefetch(float* Ks, float* Vt,
                                              const float* __restrict__ qkv,
                                              const float* __restrict__ vthead,
                                              size_t tok0, int h, int kt,
                                              int stage, int tid) {
#pragma unroll
    for (int i = 0; i < 4; i++) {
        int idx = tid + i * 256;
        int r   = idx >> 4;          // K: key row   | V^T: hd row
        int c4  = (idx & 15) * 4;    // K: hd col    | V^T: token col
        cp16(&Ks[stage * K_STAGE + r * K_PAD + c4],
             &qkv[(tok0 + kt * 64 + r) * (size_t)QKVN + h * HD + c4 + DIM]);
        cp16(&Vt[stage * VT_STAGE + r * VT_PAD + c4],
             &vthead[(size_t)r * SEQ + kt * 64 + c4]);
    }
    cp_commit();
}

__global__ void __launch_bounds__(256, 2)
attn_tf32_kernel(const float* __restrict__ qkv, const float* __restrict__ vT,
                 float* __restrict__ att) {
    extern __shared__ float smf[];
    float* Qs = smf;                          // [128][QP_PAD]; reused as Ps
    float* Ks = smf + 128 * QP_PAD;           // [2][64][K_PAD]
    float* Vt = Ks + 2 * K_STAGE;             // [2][64][VT_PAD]

    const int tid  = threadIdx.x;
    const int lane = tid & 31;
    const int warp = tid >> 5;
    const int g    = lane >> 2;
    const int tg   = lane & 3;
    const int bq   = gridDim.x - 1 - blockIdx.x;   // largest tiles first
    const int bh   = blockIdx.y;
    const int b    = bh >> 4;
    const int h    = bh & 15;
    const size_t tok0 = (size_t)b * SEQ;
    const int qr   = warp * 16;

    // ldmatrix per-lane constants
    const int l7  = lane & 7;
    const int rA8 = ((lane >> 3) & 1) * 8;
    const int gA  = lane >> 4;
    const int rB8 = (lane >> 4) * 8;
    const int gB  = (lane >> 3) & 1;

    const int ktmax = 2 * bq + 2;
    const float* vthead = vT + (size_t)bh * HD * SEQ;

    attn_prefetch(Ks, Vt, qkv, vthead, tok0, h, 0, 0, tid);

    // Q: pre-rounded; *0.125 is exact
#pragma unroll
    for (int i = 0; i < 8; i++) {
        int idx = tid + i * 256;
        int r   = idx >> 4;
        int c4  = (idx & 15) * 4;
        float4 v = *(const float4*)&qkv[(tok0 + bq * 128 + r) * QKVN + h * HD + c4];
        Qs[r * QP_PAD + c4 + 0] = v.x * 0.125f;
        Qs[r * QP_PAD + c4 + 1] = v.y * 0.125f;
        Qs[r * QP_PAD + c4 + 2] = v.z * 0.125f;
        Qs[r * QP_PAD + c4 + 3] = v.w * 0.125f;
    }
    __syncthreads();

    // Hoist Q fragments via ldmatrix (A-pattern)
    unsigned qf[8][4];
    {
        const uint32_t qrow = smem_u32(Qs) + (qr + rA8 + l7) * (QP_PAD * 4u) + gA * 16u;
#pragma unroll
        for (int k8 = 0; k8 < 8; k8++)
            ldsm4(qf[k8][0], qf[k8][1], qf[k8][2], qf[k8][3], qrow + k8 * 32u);
    }
    __syncthreads();

    unsigned* Ps = (unsigned*)Qs;
    const uint32_t prow = smem_u32(Ps) + (qr + rA8 + l7) * (QP_PAD * 4u) + gA * 16u;
    uint32_t krow[4], vrow[4];
#pragma unroll
    for (int np = 0; np < 4; np++) {
        krow[np] = smem_u32(Ks) + (np * 16 + rB8 + l7) * (K_PAD * 4u) + gB * 16u;
        vrow[np] = smem_u32(Vt) + (np * 16 + rB8 + l7) * (VT_PAD * 4u) + gB * 16u;
    }

    float oacc[8][4];
#pragma unroll
    for (int n = 0; n < 8; n++)
#pragma unroll
        for (int i = 0; i < 4; i++) oacc[n][i] = 0.0f;
    float mrow[2] = {-INFINITY, -INFINITY};
    float lrow[2] = {0.0f, 0.0f};

    const int r0g = bq * 128 + qr + g;
    const int r1g = r0g + 8;
    const int warp_row_min = bq * 128 + qr;
    const int warp_row_max = warp_row_min + 15;

#pragma unroll 1
    for (int kt = 0; kt < ktmax; kt++) {
        cp_wait<0>();
        __syncthreads();   // all warps done with iter kt-1 -> stage (kt+1)&1 free
        if (kt + 1 < ktmax)
            attn_prefetch(Ks, Vt, qkv, vthead, tok0, h, kt + 1, (kt + 1) & 1, tid);

        // Fully-masked tile for this warp contributes 0 — skip.
        if (warp_row_max < kt * 64) continue;

        const uint32_t kstage = (uint32_t)((kt & 1) * K_STAGE * 4);
        const uint32_t vstage = (uint32_t)((kt & 1) * VT_STAGE * 4);

        float sacc[8][4];
#pragma unroll
        for (int n = 0; n < 8; n++)
#pragma unroll
            for (int i = 0; i < 4; i++) sacc[n][i] = 0.0f;
#pragma unroll
        for (int k8 = 0; k8 < 8; k8++) {
#pragma unroll
            for (int np = 0; np < 4; np++) {
                unsigned b0, b1, b2, b3;
                ldsm4(b0, b1, b2, b3, krow[np] + kstage + k8 * 32u);
                mma_tf32(sacc[2 * np],     qf[k8], b0, b1);
                mma_tf32(sacc[2 * np + 1], qf[k8], b2, b3);
            }
        }

        // Mask iff tile max col can exceed warp MIN row.
        if (kt * 64 + 63 > warp_row_min) {
#pragma unroll
            for (int n = 0; n < 8; n++) {
#pragma unroll
                for (int ci = 0; ci < 4; ci++) {
                    int col = kt * 64 + n * 8 + tg * 2 + (ci & 1);
                    int rowg = (ci < 2) ? r0g : r1g;
                    if (col > rowg) sacc[n][ci] = -INFINITY;
                }
            }
        }

        float mx0 = -INFINITY, mx1 = -INFINITY;
#pragma unroll
        for (int n = 0; n < 8; n++) {
            mx0 = fmaxf(mx0, fmaxf(sacc[n][0], sacc[n][1]));
            mx1 = fmaxf(mx1, fmaxf(sacc[n][2], sacc[n][3]));
        }
#pragma unroll
        for (int off = 1; off <= 2; off <<= 1) {
            mx0 = fmaxf(mx0, __shfl_xor_sync(0xffffffffu, mx0, off));
            mx1 = fmaxf(mx1, __shfl_xor_sync(0xffffffffu, mx1, off));
        }
        float mn0 = fmaxf(mrow[0], mx0);
        float mn1 = fmaxf(mrow[1], mx1);
        float al0 = __expf(mrow[0] - mn0);
        float al1 = __expf(mrow[1] - mn1);

        float rs0 = 0.0f, rs1 = 0.0f;
#pragma unroll
        for (int n = 0; n < 8; n++) {
            sacc[n][0] = __expf(sacc[n][0] - mn0);
            sacc[n][1] = __expf(sacc[n][1] - mn0);
            sacc[n][2] = __expf(sacc[n][2] - mn1);
            sacc[n][3] = __expf(sacc[n][3] - mn1);
            rs0 += sacc[n][0] + sacc[n][1];
            rs1 += sacc[n][2] + sacc[n][3];
        }
#pragma unroll
        for (int off = 1; off <= 2; off <<= 1) {
            rs0 += __shfl_xor_sync(0xffffffffu, rs0, off);
            rs1 += __shfl_xor_sync(0xffffffffu, rs1, off);
        }
        lrow[0] = lrow[0] * al0 + rs0;
        lrow[1] = lrow[1] * al1 + rs1;
        mrow[0] = mn0;
        mrow[1] = mn1;
#pragma unroll
        for (int n = 0; n < 8; n++) {
            oacc[n][0] *= al0; oacc[n][1] *= al0;
            oacc[n][2] *= al1; oacc[n][3] *= al1;
        }

#pragma unroll
        for (int n = 0; n < 8; n++) {
            *(uint2*)&Ps[(qr + g) * QP_PAD + n * 8 + tg * 2] =
                make_uint2(f2tf(sacc[n][0]), f2tf(sacc[n][1]));
            *(uint2*)&Ps[(qr + g + 8) * QP_PAD + n * 8 + tg * 2] =
                make_uint2(f2tf(sacc[n][2]), f2tf(sacc[n][3]));
        }
        __syncwarp();

        // O += P @ V : A = P (ldsm A-pattern), B = V^T (ldsm B-pattern)
#pragma unroll
        for (int k8 = 0; k8 < 8; k8++) {
            unsigned pa[4];
            ldsm4(pa[0], pa[1], pa[2], pa[3], prow + k8 * 32u);
#pragma unroll
            for (int np = 0; np < 4; np++) {
                unsigned b0, b1, b2, b3;
                ldsm4(b0, b1, b2, b3, vrow[np] + vstage + k8 * 32u);
                mma_tf32(oacc[2 * np],     pa, b0, b1);
                mma_tf32(oacc[2 * np + 1], pa, b2, b3);
            }
        }
    }

    float inv0 = 1.0f / lrow[0];
    float inv1 = 1.0f / lrow[1];
    size_t row0 = tok0 + bq * 128 + qr + g;
#pragma unroll
    for (int n = 0; n < 8; n++) {
        int col = h * HD + n * 8 + tg * 2;
        *(float2*)&att[row0 * DIM + col] =
            make_float2(__uint_as_float(f2tf(oacc[n][0] * inv0)),
                        __uint_as_float(f2tf(oacc[n][1] * inv0)));
        *(float2*)&att[(row0 + 8) * DIM + col] =
            make_float2(__uint_as_float(f2tf(oacc[n][2] * inv1)),
                        __uint_as_float(f2tf(oacc[n][3] * inv1)));
    }
}

// ----------------------------------------------------------------------------
extern "C" void kernel_launch(void* const* d_in, const int* in_sizes, int n_in,
                              void* d_out, int out_size) {
    const float* x     = (const float*)d_in[0];
    const float* W_qkv = (const float*)d_in[1];
    const float* W_out = (const float*)d_in[2];
    float* out = (float*)d_out;

    float *qkv_buf, *vt_buf, *att_buf, *xr, *wqr, *wor;
    cudaGetSymbolAddress((void**)&qkv_buf, g_qkv);
    cudaGetSymbolAddress((void**)&vt_buf,  g_vT);
    cudaGetSymbolAddress((void**)&att_buf, g_att);
    cudaGetSymbolAddress((void**)&xr,  g_xr);
    cudaGetSymbolAddress((void**)&wqr, g_wqr);
    cudaGetSymbolAddress((void**)&wor, g_wor);

    cudaFuncSetAttribute(gemm_tf32_kernel<true>,
                         cudaFuncAttributeMaxDynamicSharedMemorySize, GEMM_SMEM);
    cudaFuncSetAttribute(gemm_tf32_kernel<false>,
                         cudaFuncAttributeMaxDynamicSharedMemorySize, GEMM_SMEM);
    cudaFuncSetAttribute(attn_tf32_kernel,
                         cudaFuncAttributeMaxDynamicSharedMemorySize, ATTN_SMEM);

    // 0) One-time rounding pre-pass
    {
        int n4x = MTOK * DIM / 4;
        round_tf32_kernel<<<(n4x + 255) / 256, 256>>>(x, xr, n4x);
        int n4q = QKVN * DIM / 4;
        round_tf32_kernel<<<(n4q + 255) / 256, 256>>>(W_qkv, wqr, n4q);
        int n4o = DIM * DIM / 4;
        round_tf32_kernel<<<(n4o + 255) / 256, 256>>>(W_out, wor, n4o);
    }

    // 1) QKV projection (V third written transposed into g_vT)
    {
        dim3 grid(QKVN / 128, MTOK / 128);
        gemm_tf32_kernel<true><<<grid, 256, GEMM_SMEM>>>(xr, wqr, qkv_buf, vt_buf,
                                                         MTOK, QKVN, DIM);
    }
    // 2) Causal flash attention
    {
        dim3 grid(SEQ / 128, BSZ * NH);
        attn_tf32_kernel<<<grid, 256, ATTN_SMEM>>>(qkv_buf, vt_buf, att_buf);
    }
    // 3) Output projection
    {
        dim3 grid(DIM / 128, MTOK / 128);
        gemm_tf32_kernel<false><<<grid, 256, GEMM_SMEM>>>(att_buf, wor, out, nullptr,
                                                          MTOK, DIM, DIM);
    }
}